// round 1
// baseline (speedup 1.0000x reference)
#include <cuda_runtime.h>
#include <math.h>
#include <stdint.h>

#define AN 196416
#define NC 80
#define KK 1000
#define KP 1024

// Transposed scores [NC][AN]
__device__ float g_scoresT[(size_t)NC * AN];

// ---------------------------------------------------------------------------
// Kernel 1: transpose classification [AN, NC] -> [NC, AN]
// ---------------------------------------------------------------------------
__global__ void transpose_kernel(const float* __restrict__ cls) {
    __shared__ float tile[32][33];
    int a0 = blockIdx.x * 32;
    int c0 = blockIdx.y * 32;
    int tx = threadIdx.x, ty = threadIdx.y;
#pragma unroll
    for (int r = ty; r < 32; r += 8) {
        int c = c0 + tx;
        tile[r][tx] = (c < NC) ? cls[(size_t)(a0 + r) * NC + c] : 0.0f;
    }
    __syncthreads();
#pragma unroll
    for (int r = ty; r < 32; r += 8) {
        int c = c0 + r;
        if (c < NC) g_scoresT[(size_t)c * AN + (a0 + tx)] = tile[tx][r];
    }
}

// ---------------------------------------------------------------------------
// Fused per-class kernel: radix-select top-1000 -> sort -> decode -> NMS -> out
// ---------------------------------------------------------------------------
struct Smem {
    unsigned int mask[KP * 32];       // 128KB NMS bitmask; first 32KB reused as per-warp hist
    unsigned long long sortbuf[KP];   // 8KB
    float4 boxes[KP];                 // 16KB
    float score[KP];                  // 4KB
    int tie[2048];                    // 8KB
    unsigned char validf[KP];         // 1KB
    unsigned int hist[256];           // 1KB
    unsigned int removedW[32];
    unsigned int s_prefix;
    int s_target;
    int s_cntG;
    int s_cntT;
};

__device__ __forceinline__ unsigned int order_key(float x) {
    unsigned int u = __float_as_uint(x);
    return (u & 0x80000000u) ? ~u : (u | 0x80000000u);
}

__global__ __launch_bounds__(1024, 1)
void perclass_kernel(const float* __restrict__ reg,
                     const float* __restrict__ anc,
                     float* __restrict__ out) {
    extern __shared__ char smraw[];
    Smem& sm = *reinterpret_cast<Smem*>(smraw);
    const int c = blockIdx.x;
    const int tid = threadIdx.x;
    const int lane = tid & 31;
    const int wid = tid >> 5;

    const float4* __restrict__ row4 =
        reinterpret_cast<const float4*>(g_scoresT + (size_t)c * AN);
    unsigned int (*whist)[256] = reinterpret_cast<unsigned int (*)[256]>(sm.mask);

    // ---------------- exact radix select (4 passes, 8 bits each) ------------
    unsigned int prefix = 0;
    if (tid == 0) sm.s_target = KK;
    __syncthreads();

    for (int shift = 24; shift >= 0; shift -= 8) {
        for (int i = tid; i < 32 * 256; i += 1024)
            reinterpret_cast<unsigned int*>(whist)[i] = 0;
        __syncthreads();

        const unsigned int pmask = (shift == 24) ? 0u : (0xFFFFFFFFu << (shift + 8));
        unsigned int* myhist = whist[wid];
        for (int i = tid; i < AN / 4; i += 1024) {
            float4 v = row4[i];
            unsigned int k;
#define DOHIST(x)                                                            \
            k = order_key(x);                                                \
            if ((k & pmask) == prefix)                                       \
                atomicAdd(&myhist[(k >> shift) & 255], 1u);
            DOHIST(v.x) DOHIST(v.y) DOHIST(v.z) DOHIST(v.w)
#undef DOHIST
        }
        __syncthreads();

        if (tid < 256) {
            unsigned int s = 0;
#pragma unroll
            for (int w = 0; w < 32; ++w) s += whist[w][tid];
            sm.hist[tid] = s;
        }
        __syncthreads();

        if (tid == 0) {
            int t = sm.s_target;
            unsigned int cum = 0;
            for (int b = 255; b >= 0; --b) {
                unsigned int h = sm.hist[b];
                if (cum + h >= (unsigned int)t) {
                    sm.s_target = t - (int)cum;
                    sm.s_prefix = prefix | ((unsigned int)b << shift);
                    break;
                }
                cum += h;
            }
        }
        __syncthreads();
        prefix = sm.s_prefix;
        __syncthreads();
    }

    const unsigned int T = prefix;          // exact key of the K-th largest
    // ---------------- compaction -------------------------------------------
    if (tid == 0) { sm.s_cntG = 0; sm.s_cntT = 0; }
    __syncthreads();

    for (int i = tid; i < AN / 4; i += 1024) {
        float4 v = row4[i];
        int base = i * 4;
        unsigned int k;
#define DOCOMP(x, off)                                                        \
        k = order_key(x);                                                     \
        if (k > T) {                                                          \
            int p = atomicAdd(&sm.s_cntG, 1);                                 \
            sm.sortbuf[p] =                                                   \
                ((unsigned long long)(~k) << 32) | (unsigned int)(base + off);\
        } else if (k == T) {                                                  \
            int p = atomicAdd(&sm.s_cntT, 1);                                 \
            if (p < 2048) sm.tie[p] = base + off;                             \
        }
        DOCOMP(v.x, 0) DOCOMP(v.y, 1) DOCOMP(v.z, 2) DOCOMP(v.w, 3)
#undef DOCOMP
    }
    __syncthreads();

    const int numG = sm.s_cntG;
    const int needed = sm.s_target;
    int cntT = sm.s_cntT; if (cntT > 2048) cntT = 2048;

    // pick smallest `needed` indices among ties (jax top_k = lower index first)
    if (tid == 0 && cntT > needed) {
        for (int s = 0; s < needed; ++s) {
            int mi = s;
            for (int t = s + 1; t < cntT; ++t)
                if (sm.tie[t] < sm.tie[mi]) mi = t;
            int tmp = sm.tie[s]; sm.tie[s] = sm.tie[mi]; sm.tie[mi] = tmp;
        }
    }
    __syncthreads();
    if (tid < needed)
        sm.sortbuf[numG + tid] =
            ((unsigned long long)(~T) << 32) | (unsigned int)sm.tie[tid];
    if (tid >= KK && tid < KP)
        sm.sortbuf[tid] = 0xFFFFFFFFFFFFFFFFull;
    __syncthreads();

    // ---------------- bitonic sort (ascending u64 = score desc, idx asc) ---
    for (int k2 = 2; k2 <= KP; k2 <<= 1) {
        for (int j = k2 >> 1; j > 0; j >>= 1) {
            int ixj = tid ^ j;
            if (ixj > tid) {
                unsigned long long a = sm.sortbuf[tid];
                unsigned long long b = sm.sortbuf[ixj];
                bool asc = ((tid & k2) == 0);
                if ((a > b) == asc) { sm.sortbuf[tid] = b; sm.sortbuf[ixj] = a; }
            }
            __syncthreads();
        }
    }

    // ---------------- decode + clip gathered boxes -------------------------
    if (tid < KK) {
        unsigned long long kv = sm.sortbuf[tid];
        unsigned int kk = ~(unsigned int)(kv >> 32);
        unsigned int u = (kk & 0x80000000u) ? (kk ^ 0x80000000u) : ~kk;
        float sc = __uint_as_float(u);
        int idx = (int)(kv & 0xFFFFFFFFull);

        float4 a = reinterpret_cast<const float4*>(anc)[idx];
        float4 r = reinterpret_cast<const float4*>(reg)[idx];
        float wa = a.z - a.x, ha = a.w - a.y;
        float cxa = a.x + 0.5f * wa, cya = a.y + 0.5f * ha;
        float cx = cxa + (r.x * 0.1f) * wa;
        float cy = cya + (r.y * 0.1f) * ha;
        float w = __expf(r.z * 0.2f) * wa;
        float h = __expf(r.w * 0.2f) * ha;
        float4 b;
        b.x = fminf(fmaxf(cx - 0.5f * w, 0.0f), 1024.0f);
        b.y = fminf(fmaxf(cy - 0.5f * h, 0.0f), 1024.0f);
        b.z = fminf(fmaxf(cx + 0.5f * w, 0.0f), 1024.0f);
        b.w = fminf(fmaxf(cy + 0.5f * h, 0.0f), 1024.0f);
        sm.boxes[tid] = b;
        sm.score[tid] = sc;
        sm.validf[tid] = (sc > 0.05f) ? 1 : 0;
    } else {
        sm.boxes[tid] = make_float4(0.f, 0.f, 0.f, 0.f);
        sm.score[tid] = 0.0f;
        sm.validf[tid] = 0;
    }
    __syncthreads();

    // ---------------- NMS bitmask: thread tid owns row i=tid ----------------
    {
        float4 bi = sm.boxes[tid];
        float areai = (bi.z - bi.x) * (bi.w - bi.y);
        for (int wj = 0; wj < 32; ++wj) {
            unsigned int bits = 0;
            int jbase = wj << 5;
            if (jbase + 31 > tid) {
                for (int jj = 0; jj < 32; ++jj) {
                    int j = jbase + jj;
                    if (j > tid && j < KK) {
                        float4 bj = sm.boxes[j];   // broadcast, conflict-free
                        float xx1 = fmaxf(bi.x, bj.x);
                        float yy1 = fmaxf(bi.y, bj.y);
                        float xx2 = fminf(bi.z, bj.z);
                        float yy2 = fminf(bi.w, bj.w);
                        float inter = fmaxf(xx2 - xx1, 0.f) * fmaxf(yy2 - yy1, 0.f);
                        float aj = (bj.z - bj.x) * (bj.w - bj.y);
                        float iou = inter / (areai + aj - inter + 1e-8f);
                        if (iou > 0.5f) bits |= 1u << jj;
                    }
                }
            }
            if (tid < KK) sm.mask[tid * 32 + wj] = bits;
        }
    }
    __syncthreads();

    // serial greedy reduce on warp 0 (suppress bits for i only set by i' < i,
    // so final removed bit == bit state at step i)
    if (wid == 0) {
        unsigned int removed = 0;  // lane owns word `lane` (bits j in [32*lane, 32*lane+32))
        for (int i = 0; i < KK; ++i) {
            unsigned int rm = __shfl_sync(0xFFFFFFFFu, removed, i >> 5);
            bool kept = sm.validf[i] && !((rm >> (i & 31)) & 1u);
            if (kept) removed |= sm.mask[i * 32 + lane];
        }
        sm.removedW[lane] = removed;
    }
    __syncthreads();

    // ---------------- outputs ----------------------------------------------
    if (tid < KK) {
        int o = c * KK + tid;
        unsigned int rw = sm.removedW[tid >> 5];
        bool kp = sm.validf[tid] && !((rw >> (tid & 31)) & 1u);
        out[o] = kp ? sm.score[tid] : 0.0f;                       // scores
        out[NC * KK + o] = kp ? (float)c : -1.0f;                 // labels
        float4 bb = kp ? sm.boxes[tid] : make_float4(0.f, 0.f, 0.f, 0.f);
        reinterpret_cast<float4*>(out + 2 * NC * KK)[o] = bb;     // boxes
        out[6 * NC * KK + o] = kp ? 1.0f : 0.0f;                  // keep
    }
}

// ---------------------------------------------------------------------------
extern "C" void kernel_launch(void* const* d_in, const int* in_sizes, int n_in,
                              void* d_out, int out_size) {
    const float* cls = (const float*)d_in[0];   // [1, AN, NC]
    const float* reg = (const float*)d_in[1];   // [1, AN, 4]
    const float* anc = (const float*)d_in[2];   // [1, AN, 4]
    float* out = (float*)d_out;

    dim3 tb(32, 8);
    dim3 tg(AN / 32, (NC + 31) / 32);
    transpose_kernel<<<tg, tb>>>(cls);

    cudaFuncSetAttribute(perclass_kernel,
                         cudaFuncAttributeMaxDynamicSharedMemorySize,
                         (int)sizeof(Smem));
    perclass_kernel<<<NC, 1024, sizeof(Smem)>>>(reg, anc, out);
}

// round 2
// speedup vs baseline: 1.9392x; 1.9392x over previous
#include <cuda_runtime.h>
#include <math.h>
#include <stdint.h>

#define AN 196416
#define NC 80
#define KK 1000
#define KP 1024
#define CAP 2048   // candidate/sort capacity

// Transposed scores [NC][AN]
__device__ float g_scoresT[(size_t)NC * AN];

// ---------------------------------------------------------------------------
// Kernel 1: transpose classification [AN, NC] -> [NC, AN] (float4 stores)
// ---------------------------------------------------------------------------
__global__ void transpose_kernel(const float* __restrict__ cls) {
    __shared__ float tile[32][33];
    int a0 = blockIdx.x * 32;
    int c0 = blockIdx.y * 32;
    int tid = threadIdx.x;          // 256
    int tx = tid & 31, ty = tid >> 5;
#pragma unroll
    for (int r = ty; r < 32; r += 8) {
        int c = c0 + tx;
        tile[r][tx] = (c < NC) ? cls[(size_t)(a0 + r) * NC + c] : 0.0f;
    }
    __syncthreads();
    int cc = tid >> 3, q = tid & 7;  // 32 classes x 8 anchor-quads
    int c = c0 + cc;
    if (c < NC) {
        float4 v;
        v.x = tile[q * 4 + 0][cc];
        v.y = tile[q * 4 + 1][cc];
        v.z = tile[q * 4 + 2][cc];
        v.w = tile[q * 4 + 3][cc];
        *reinterpret_cast<float4*>(&g_scoresT[(size_t)c * AN + a0 + q * 4]) = v;
    }
}

// ---------------------------------------------------------------------------
// Fused per-class kernel
// ---------------------------------------------------------------------------
struct Smem {
    unsigned int mask[KP * 32];        // 128KB NMS bitmask; first 64KB reused as hist
    unsigned long long sortbuf[CAP];   // 16KB
    float4 boxes[KP];                  // 16KB
    float score[KP];                   // 4KB
    float area[KP];                    // 4KB
    unsigned char validf[KP];          // 1KB
    unsigned int totals[16];
    unsigned int removedW[32];
    float s_blo;
    int s_above;
    int s_cand;
    int s_cnt;
};

__device__ __forceinline__ unsigned int order_key(float x) {
    unsigned int u = __float_as_uint(x);
    return (u & 0x80000000u) ? ~u : (u | 0x80000000u);
}

__global__ __launch_bounds__(1024, 1)
void perclass_kernel(const float* __restrict__ reg,
                     const float* __restrict__ anc,
                     float* __restrict__ out) {
    extern __shared__ char smraw[];
    Smem& sm = *reinterpret_cast<Smem*>(smraw);
    const int c = blockIdx.x;
    const int tid = threadIdx.x;
    const int lane = tid & 31;
    const int wid = tid >> 5;

    const float4* __restrict__ row4 =
        reinterpret_cast<const float4*>(g_scoresT + (size_t)c * AN);
    unsigned int* hist = sm.mask;   // 16 bins x 1024 threads, [bin*1024 + tid]

    // ============ hierarchical 16-way selection (atomic-free hists) ========
    float blo = 0.0f;
    float bwid = 1.0f / 16.0f;
    int aboveCnt = 0;
    int candTotal = AN;

    for (int level = 0; level < 4; ++level) {
#pragma unroll
        for (int b = 0; b < 16; ++b) hist[b * 1024 + tid] = 0;
        __syncthreads();

        const float inv = 1.0f / bwid;
        if (level == 0) {
            for (int i = tid; i < AN / 4; i += 1024) {
                float4 v = row4[i];
#define DOH0(x) { int b = (int)((x) * 16.0f);                                \
                  b = b < 0 ? 0 : (b > 15 ? 15 : b);                         \
                  hist[b * 1024 + tid] += 1u; }
                DOH0(v.x) DOH0(v.y) DOH0(v.z) DOH0(v.w)
#undef DOH0
            }
        } else {
            for (int i = tid; i < AN / 4; i += 1024) {
                float4 v = row4[i];
#define DOH(x) { float t = ((x) - blo) * inv;                                \
                 if ((x) >= blo && t < 16.0f) {                              \
                     int b = (int)t;                                         \
                     hist[b * 1024 + tid] += 1u; } }
                DOH(v.x) DOH(v.y) DOH(v.z) DOH(v.w)
#undef DOH
            }
        }
        __syncthreads();

        // reduce: warp w sums bin w over 1024 threads (conflict-free)
        if (wid < 16) {
            unsigned int s = 0;
#pragma unroll
            for (int k = 0; k < 32; ++k) s += hist[wid * 1024 + k * 32 + lane];
#pragma unroll
            for (int o = 16; o > 0; o >>= 1) s += __shfl_down_sync(0xFFFFFFFFu, s, o);
            if (lane == 0) sm.totals[wid] = s;
        }
        __syncthreads();

        if (tid == 0) {
            int cum = aboveCnt;
            int b = 15;
            for (; b >= 0; --b) {
                cum += (int)sm.totals[b];
                if (cum >= KK) break;
            }
            if (b < 0) b = 0;
            sm.s_blo = blo + (float)b * bwid;
            sm.s_above = cum - (int)sm.totals[b];
            sm.s_cand = cum;
        }
        __syncthreads();
        blo = sm.s_blo;
        aboveCnt = sm.s_above;
        candTotal = sm.s_cand;
        bwid *= (1.0f / 16.0f);
        __syncthreads();
        if (candTotal <= 1800) break;
    }

    // ============ compaction (thr has one-sub-bin slack for fp safety) =====
    const float thr = blo - bwid;
    if (tid == 0) sm.s_cnt = 0;
    __syncthreads();

    for (int i = tid; i < AN / 4; i += 1024) {
        float4 v = row4[i];
        int base = i * 4;
#define DOC(x, off)                                                          \
        if ((x) >= thr) {                                                    \
            int p = atomicAdd(&sm.s_cnt, 1);                                 \
            if (p < CAP)                                                     \
                sm.sortbuf[p] = ((unsigned long long)(~order_key(x)) << 32)  \
                                | (unsigned int)(base + off);                \
        }
        DOC(v.x, 0) DOC(v.y, 1) DOC(v.z, 2) DOC(v.w, 3)
#undef DOC
    }
    __syncthreads();
    {
        int cnt = sm.s_cnt; if (cnt > CAP) cnt = CAP;
        for (int i = cnt + tid; i < CAP; i += 1024)
            sm.sortbuf[i] = 0xFFFFFFFFFFFFFFFFull;
    }
    __syncthreads();

    // ============ bitonic sort of 2048 (asc u64 = score desc, idx asc) =====
    for (int k2 = 2; k2 <= CAP; k2 <<= 1) {
        for (int j = k2 >> 1; j > 0; j >>= 1) {
            int i1 = ((tid & ~(j - 1)) << 1) | (tid & (j - 1));
            int i2 = i1 | j;
            unsigned long long a = sm.sortbuf[i1];
            unsigned long long b = sm.sortbuf[i2];
            bool asc = ((i1 & k2) == 0);
            if ((a > b) == asc) { sm.sortbuf[i1] = b; sm.sortbuf[i2] = a; }
            __syncthreads();
        }
    }

    // ============ decode + clip ============================================
    if (tid < KK) {
        unsigned long long kv = sm.sortbuf[tid];
        unsigned int kk = ~(unsigned int)(kv >> 32);
        unsigned int u = (kk & 0x80000000u) ? (kk ^ 0x80000000u) : ~kk;
        float sc = __uint_as_float(u);
        int idx = (int)(kv & 0xFFFFFFFFull);

        float4 a = reinterpret_cast<const float4*>(anc)[idx];
        float4 r = reinterpret_cast<const float4*>(reg)[idx];
        float wa = a.z - a.x, ha = a.w - a.y;
        float cxa = a.x + 0.5f * wa, cya = a.y + 0.5f * ha;
        float cx = cxa + (r.x * 0.1f) * wa;
        float cy = cya + (r.y * 0.1f) * ha;
        float w = __expf(r.z * 0.2f) * wa;
        float h = __expf(r.w * 0.2f) * ha;
        float4 b;
        b.x = fminf(fmaxf(cx - 0.5f * w, 0.0f), 1024.0f);
        b.y = fminf(fmaxf(cy - 0.5f * h, 0.0f), 1024.0f);
        b.z = fminf(fmaxf(cx + 0.5f * w, 0.0f), 1024.0f);
        b.w = fminf(fmaxf(cy + 0.5f * h, 0.0f), 1024.0f);
        sm.boxes[tid] = b;
        sm.area[tid] = (b.z - b.x) * (b.w - b.y);
        sm.score[tid] = sc;
        sm.validf[tid] = (sc > 0.05f) ? 1 : 0;
    } else {
        sm.boxes[tid] = make_float4(0.f, 0.f, 0.f, 0.f);
        sm.area[tid] = 0.0f;
        sm.score[tid] = 0.0f;
        sm.validf[tid] = 0;
    }
    __syncthreads();

    // ============ NMS bitmask (division-free IoU) ==========================
    {
        float4 bi = sm.boxes[tid];
        float areai = sm.area[tid];
        int wj0 = tid >> 5;
        for (int wj = 0; wj < 32; ++wj) {
            unsigned int bits = 0;
            if (wj >= wj0) {
                int jbase = wj << 5;
#pragma unroll 8
                for (int jj = 0; jj < 32; ++jj) {
                    int j = jbase + jj;
                    if (j > tid && j < KK) {
                        float4 bj = sm.boxes[j];        // broadcast LDS
                        float xx1 = fmaxf(bi.x, bj.x);
                        float yy1 = fmaxf(bi.y, bj.y);
                        float xx2 = fminf(bi.z, bj.z);
                        float yy2 = fminf(bi.w, bj.w);
                        float inter = fmaxf(xx2 - xx1, 0.f) * fmaxf(yy2 - yy1, 0.f);
                        float den = areai + sm.area[j] - inter + 1e-8f;
                        if (inter > 0.5f * den) bits |= 1u << jj;
                    }
                }
            }
            if (tid < KK) sm.mask[tid * 32 + wj] = bits;
        }
    }
    __syncthreads();

    // serial greedy reduce on warp 0
    if (wid == 0) {
        unsigned int removed = 0;   // lane owns word `lane`
        for (int i = 0; i < KK; ++i) {
            unsigned int rm = __shfl_sync(0xFFFFFFFFu, removed, i >> 5);
            bool kept = sm.validf[i] && !((rm >> (i & 31)) & 1u);
            if (kept) removed |= sm.mask[i * 32 + lane];
        }
        sm.removedW[lane] = removed;
    }
    __syncthreads();

    // ============ outputs ==================================================
    if (tid < KK) {
        int o = c * KK + tid;
        unsigned int rw = sm.removedW[tid >> 5];
        bool kp = sm.validf[tid] && !((rw >> (tid & 31)) & 1u);
        out[o] = kp ? sm.score[tid] : 0.0f;                       // scores
        out[NC * KK + o] = kp ? (float)c : -1.0f;                 // labels
        float4 bb = kp ? sm.boxes[tid] : make_float4(0.f, 0.f, 0.f, 0.f);
        reinterpret_cast<float4*>(out + 2 * NC * KK)[o] = bb;     // boxes
        out[6 * NC * KK + o] = kp ? 1.0f : 0.0f;                  // keep
    }
}

// ---------------------------------------------------------------------------
extern "C" void kernel_launch(void* const* d_in, const int* in_sizes, int n_in,
                              void* d_out, int out_size) {
    const float* cls = (const float*)d_in[0];   // [1, AN, NC]
    const float* reg = (const float*)d_in[1];   // [1, AN, 4]
    const float* anc = (const float*)d_in[2];   // [1, AN, 4]
    float* out = (float*)d_out;

    dim3 tb(256);
    dim3 tg(AN / 32, (NC + 31) / 32);
    transpose_kernel<<<tg, tb>>>(cls);

    cudaFuncSetAttribute(perclass_kernel,
                         cudaFuncAttributeMaxDynamicSharedMemorySize,
                         (int)sizeof(Smem));
    perclass_kernel<<<NC, 1024, sizeof(Smem)>>>(reg, anc, out);
}

// round 3
// speedup vs baseline: 2.8382x; 1.4636x over previous
#include <cuda_runtime.h>
#include <stdint.h>

#define AN 196416
#define NC 80
#define KK 1000
#define CAP 2048
#define PARTS 12   // mask-build CTAs per class (4 warps each -> 48 warps x 11 tasks = 528)

// ---------------- global scratch ----------------
__device__ float    g_scoresT[(size_t)NC * AN];
__device__ float4   g_box  [NC * 1024];
__device__ float    g_score[NC * 1024];
__device__ unsigned g_vb   [NC * 32];
__device__ unsigned g_mask [NC * 1024 * 32];
__device__ unsigned g_diag [NC * 1024];

__device__ __forceinline__ unsigned order_key(float x) {
    unsigned u = __float_as_uint(x);
    return (u & 0x80000000u) ? ~u : (u | 0x80000000u);
}

// ---------------------------------------------------------------------------
// K1: transpose classification [AN, NC] -> [NC, AN]
// ---------------------------------------------------------------------------
__global__ void transpose_kernel(const float* __restrict__ cls) {
    __shared__ float tile[32][33];
    int c0 = blockIdx.y * 32;
    int tid = threadIdx.x;                 // 256
    int tx = tid & 31, ty = tid >> 5;
#pragma unroll
    for (int rep = 0; rep < 2; ++rep) {
        int a0 = (blockIdx.x * 2 + rep) * 32;
#pragma unroll
        for (int r = ty; r < 32; r += 8) {
            int c = c0 + tx;
            tile[r][tx] = (c < NC) ? cls[(size_t)(a0 + r) * NC + c] : 0.0f;
        }
        __syncthreads();
        int cc = tid >> 3, q = tid & 7;    // 32 classes x 8 anchor-quads
        int c = c0 + cc;
        if (c < NC) {
            float4 v;
            v.x = tile[q * 4 + 0][cc];
            v.y = tile[q * 4 + 1][cc];
            v.z = tile[q * 4 + 2][cc];
            v.w = tile[q * 4 + 3][cc];
            *reinterpret_cast<float4*>(&g_scoresT[(size_t)c * AN + a0 + q * 4]) = v;
        }
        __syncthreads();
    }
}

// ---------------------------------------------------------------------------
// K2: per-class select top-1000 -> hybrid bitonic sort -> decode -> scratch
// ---------------------------------------------------------------------------
__device__ __forceinline__ unsigned long long bx_exch(
        unsigned long long e, int j, bool asc, int lane) {
    unsigned long long p = __shfl_xor_sync(0xFFFFFFFFu, e, j);
    bool low = ((lane & j) == 0);
    bool keepmin = (low == asc);
    unsigned long long mn = (e < p) ? e : p;
    unsigned long long mx = (e < p) ? p : e;
    return keepmin ? mn : mx;
}

__global__ __launch_bounds__(1024, 1)
void select_kernel(const float* __restrict__ reg,
                   const float* __restrict__ anc) {
    extern __shared__ char dsm[];
    unsigned* hist = reinterpret_cast<unsigned*>(dsm);                    // 64KB
    unsigned long long* sb =
        reinterpret_cast<unsigned long long*>(dsm + 16 * 1024 * 4);      // 16KB

    __shared__ unsigned s_totals[16];
    __shared__ float s_blo;
    __shared__ int s_above, s_cand, s_cnt;

    const int c = blockIdx.x;
    const int tid = threadIdx.x;
    const int lane = tid & 31;
    const int wid = tid >> 5;

    const float4* __restrict__ row4 =
        reinterpret_cast<const float4*>(g_scoresT + (size_t)c * AN);

    // ---- hierarchical 16-way selection (atomic-free per-thread hists) ----
    float blo = 0.0f, bwid = 1.0f / 16.0f;
    int aboveCnt = 0, candTotal = AN;

    for (int level = 0; level < 4; ++level) {
#pragma unroll
        for (int b = 0; b < 16; ++b) hist[b * 1024 + tid] = 0;
        __syncthreads();

        const float inv = 1.0f / bwid;
        if (level == 0) {
            for (int i = tid; i < AN / 4; i += 1024) {
                float4 v = row4[i];
#define DOH0(x) { int b = (int)((x) * 16.0f);                                \
                  b = b < 0 ? 0 : (b > 15 ? 15 : b);                         \
                  hist[b * 1024 + tid] += 1u; }
                DOH0(v.x) DOH0(v.y) DOH0(v.z) DOH0(v.w)
#undef DOH0
            }
        } else {
            for (int i = tid; i < AN / 4; i += 1024) {
                float4 v = row4[i];
#define DOH(x) { float t = ((x) - blo) * inv;                                \
                 if ((x) >= blo && t < 16.0f) {                              \
                     int b = (int)t;                                         \
                     hist[b * 1024 + tid] += 1u; } }
                DOH(v.x) DOH(v.y) DOH(v.z) DOH(v.w)
#undef DOH
            }
        }
        __syncthreads();

        if (wid < 16) {
            unsigned s = 0;
#pragma unroll
            for (int k = 0; k < 32; ++k) s += hist[wid * 1024 + k * 32 + lane];
#pragma unroll
            for (int o = 16; o > 0; o >>= 1) s += __shfl_down_sync(0xFFFFFFFFu, s, o);
            if (lane == 0) s_totals[wid] = s;
        }
        __syncthreads();

        if (tid == 0) {
            int cum = aboveCnt;
            int b = 15;
            for (; b >= 0; --b) {
                cum += (int)s_totals[b];
                if (cum >= KK) break;
            }
            if (b < 0) b = 0;
            s_blo = blo + (float)b * bwid;
            s_above = cum - (int)s_totals[b];
            s_cand = cum;
        }
        __syncthreads();
        blo = s_blo; aboveCnt = s_above; candTotal = s_cand;
        bwid *= (1.0f / 16.0f);
        __syncthreads();
        if (candTotal <= 1800) break;
    }

    // ---- compaction (one-sub-bin slack) ----
    const float thr = blo - bwid;
    if (tid == 0) s_cnt = 0;
    __syncthreads();

    for (int i = tid; i < AN / 4; i += 1024) {
        float4 v = row4[i];
        int base = i * 4;
#define DOC(x, off)                                                          \
        if ((x) >= thr) {                                                    \
            int p = atomicAdd(&s_cnt, 1);                                    \
            if (p < CAP)                                                     \
                sb[p] = ((unsigned long long)(~order_key(x)) << 32)          \
                        | (unsigned)(base + off);                            \
        }
        DOC(v.x, 0) DOC(v.y, 1) DOC(v.z, 2) DOC(v.w, 3)
#undef DOC
    }
    __syncthreads();
    {
        int cnt = s_cnt; if (cnt > CAP) cnt = CAP;
        for (int i = cnt + tid; i < CAP; i += 1024)
            sb[i] = 0xFFFFFFFFFFFFFFFFull;
    }
    __syncthreads();

    // ---- hybrid bitonic sort: asc u64 = score desc, idx asc ----
    unsigned long long e0 = sb[64 * wid + lane];
    unsigned long long e1 = sb[64 * wid + 32 + lane];

    // rounds k2 = 2..16 : per-lane direction
#pragma unroll
    for (int k2 = 2; k2 <= 16; k2 <<= 1) {
#pragma unroll
        for (int j = k2 >> 1; j >= 1; j >>= 1) {
            bool a0 = ((lane & k2) == 0);
            e0 = bx_exch(e0, j, a0, lane);
            e1 = bx_exch(e1, j, a0, lane);
        }
    }
    // round k2 = 32 : e0 asc, e1 desc
#pragma unroll
    for (int j = 16; j >= 1; j >>= 1) {
        e0 = bx_exch(e0, j, true, lane);
        e1 = bx_exch(e1, j, false, lane);
    }
    // round k2 = 64 : uniform per warp
    {
        bool A = ((wid & 1) == 0);
        unsigned long long mn = (e0 < e1) ? e0 : e1;
        unsigned long long mx = (e0 < e1) ? e1 : e0;
        e0 = A ? mn : mx; e1 = A ? mx : mn;
#pragma unroll
        for (int j = 16; j >= 1; j >>= 1) {
            e0 = bx_exch(e0, j, A, lane);
            e1 = bx_exch(e1, j, A, lane);
        }
    }
    // rounds k2 = 128..2048 : smem for j>=64, registers for j<=32
    for (int k2 = 128; k2 <= CAP; k2 <<= 1) {
        sb[64 * wid + lane] = e0;
        sb[64 * wid + 32 + lane] = e1;
        __syncthreads();
        for (int j = k2 >> 1; j >= 64; j >>= 1) {
            int i1 = ((tid & ~(j - 1)) << 1) | (tid & (j - 1));
            int i2 = i1 | j;
            unsigned long long a = sb[i1];
            unsigned long long b = sb[i2];
            bool asc = ((i1 & k2) == 0);
            if ((a > b) == asc) { sb[i1] = b; sb[i2] = a; }
            __syncthreads();
        }
        e0 = sb[64 * wid + lane];
        e1 = sb[64 * wid + 32 + lane];
        bool A = (((wid * 64) & k2) == 0);
        unsigned long long mn = (e0 < e1) ? e0 : e1;
        unsigned long long mx = (e0 < e1) ? e1 : e0;
        e0 = A ? mn : mx; e1 = A ? mx : mn;
#pragma unroll
        for (int j = 16; j >= 1; j >>= 1) {
            e0 = bx_exch(e0, j, A, lane);
            e1 = bx_exch(e1, j, A, lane);
        }
    }
    sb[64 * wid + lane] = e0;
    sb[64 * wid + 32 + lane] = e1;
    __syncthreads();

    // ---- decode + clip -> global scratch ----
    float sc = 0.0f;
    if (tid < KK) {
        unsigned long long kv = sb[tid];
        unsigned kk = ~(unsigned)(kv >> 32);
        unsigned u = (kk & 0x80000000u) ? (kk ^ 0x80000000u) : ~kk;
        sc = __uint_as_float(u);
        int idx = (int)(kv & 0xFFFFFFFFull);

        float4 a = reinterpret_cast<const float4*>(anc)[idx];
        float4 r = reinterpret_cast<const float4*>(reg)[idx];
        float wa = a.z - a.x, ha = a.w - a.y;
        float cxa = a.x + 0.5f * wa, cya = a.y + 0.5f * ha;
        float cx = cxa + (r.x * 0.1f) * wa;
        float cy = cya + (r.y * 0.1f) * ha;
        float w = __expf(r.z * 0.2f) * wa;
        float h = __expf(r.w * 0.2f) * ha;
        float4 b;
        b.x = fminf(fmaxf(cx - 0.5f * w, 0.0f), 1024.0f);
        b.y = fminf(fmaxf(cy - 0.5f * h, 0.0f), 1024.0f);
        b.z = fminf(fmaxf(cx + 0.5f * w, 0.0f), 1024.0f);
        b.w = fminf(fmaxf(cy + 0.5f * h, 0.0f), 1024.0f);
        g_box[c * 1024 + tid] = b;
        g_score[c * 1024 + tid] = sc;
    } else {
        g_box[c * 1024 + tid] = make_float4(0.f, 0.f, 0.f, 0.f);
        g_score[c * 1024 + tid] = 0.0f;
    }
    unsigned bal = __ballot_sync(0xFFFFFFFFu, (tid < KK) && (sc > 0.05f));
    if (lane == 0) g_vb[c * 32 + wid] = bal;
}

// ---------------------------------------------------------------------------
// K3: NMS bitmask build, chip-wide (528 block-pair tasks per class)
// ---------------------------------------------------------------------------
__global__ __launch_bounds__(128)
void nms_mask_kernel() {
    __shared__ float4 sbox[1024];
    __shared__ float  sarea[1024];
    const int c = blockIdx.y;
    const int p = blockIdx.x;
    const int tid = threadIdx.x;
    const int lane = tid & 31;
    const int wid = tid >> 5;

    for (int i = tid; i < 1024; i += 128) {
        float4 b = g_box[c * 1024 + i];
        sbox[i] = b;
        sarea[i] = (b.z - b.x) * (b.w - b.y);
    }
    __syncthreads();

    int gw = p * 4 + wid;          // 0..47
    int t0 = gw * 11;              // 48*11 = 528 exactly
    int bi = 0, rem = t0;
    while (rem >= 32 - bi) { rem -= 32 - bi; ++bi; }
    int bj = bi + rem;

    for (int s = 0; s < 11; ++s) {
        float4 bjb = sbox[bj * 32 + lane];
        float aj = sarea[bj * 32 + lane];
        bool diagb = (bi == bj);
        unsigned myword = 0;
#pragma unroll 8
        for (int i = 0; i < 32; ++i) {
            float4 bib = sbox[bi * 32 + i];     // broadcast
            float ai = sarea[bi * 32 + i];
            float xx1 = fmaxf(bib.x, bjb.x);
            float yy1 = fmaxf(bib.y, bjb.y);
            float xx2 = fminf(bib.z, bjb.z);
            float yy2 = fminf(bib.w, bjb.w);
            float inter = fmaxf(xx2 - xx1, 0.f) * fmaxf(yy2 - yy1, 0.f);
            float den = ai + aj - inter + 1e-8f;
            bool ok = (inter > 0.5f * den) && (!diagb || (lane > i));
            unsigned word = __ballot_sync(0xFFFFFFFFu, ok);
            if (lane == i) myword = word;
        }
        g_mask[(c * 1024 + bi * 32 + lane) * 32 + bj] = myword;
        if (diagb) g_diag[c * 1024 + bi * 32 + lane] = myword;
        if (++bj == 32) { ++bi; bj = bi; }
    }
}

// ---------------------------------------------------------------------------
// K4: serial greedy reduce + outputs (grid NC)
// ---------------------------------------------------------------------------
__global__ __launch_bounds__(1024, 1)
void nms_reduce_kernel(float* __restrict__ out) {
    extern __shared__ unsigned s_mask[];   // 32768 words = 128KB
    __shared__ unsigned s_diag[1024];
    __shared__ unsigned s_vb[32];
    __shared__ unsigned s_removed[32];

    const int c = blockIdx.x;
    const int tid = threadIdx.x;
    const int lane = tid & 31;
    const int wid = tid >> 5;

    // preload mask, zero lower-triangle words (j-block < i-block: undefined)
    const unsigned* gm = g_mask + c * 32768;
#pragma unroll
    for (int k = 0; k < 32; ++k) {
        int f = tid + k * 1024;
        int i = f >> 5, w = f & 31;
        unsigned v = gm[f];
        s_mask[f] = (w >= (i >> 5)) ? v : 0u;
    }
    s_diag[tid] = g_diag[c * 1024 + tid];
    if (tid < 32) s_vb[tid] = g_vb[c * 32 + tid];
    __syncthreads();

    if (wid == 0) {
        unsigned removed = 0;              // lane owns word `lane`
        unsigned vbl = s_vb[lane];
        for (int b = 0; b < 32; ++b) {
            unsigned rmw = __shfl_sync(0xFFFFFFFFu, removed, b);
            unsigned vbw = __shfl_sync(0xFFFFFFFFu, vbl, b);
#pragma unroll
            for (int r = 0; r < 32; ++r) {
                unsigned dgr = s_diag[b * 32 + r];                 // broadcast
                unsigned mrr = s_mask[(b * 32 + r) * 32 + lane];   // conflict-free
                bool kept = ((vbw >> r) & 1u) && !((rmw >> r) & 1u);
                if (kept) { rmw |= dgr; removed |= mrr; }
            }
        }
        s_removed[lane] = removed;
    }
    __syncthreads();

    if (tid < KK) {
        int o = c * KK + tid;
        unsigned rw = s_removed[tid >> 5];
        unsigned vb = s_vb[tid >> 5];
        bool kp = ((vb >> (tid & 31)) & 1u) && !((rw >> (tid & 31)) & 1u);
        float sc = g_score[c * 1024 + tid];
        float4 bb = g_box[c * 1024 + tid];
        out[o] = kp ? sc : 0.0f;
        out[NC * KK + o] = kp ? (float)c : -1.0f;
        reinterpret_cast<float4*>(out + 2 * NC * KK)[o] =
            kp ? bb : make_float4(0.f, 0.f, 0.f, 0.f);
        out[6 * NC * KK + o] = kp ? 1.0f : 0.0f;
    }
}

// ---------------------------------------------------------------------------
extern "C" void kernel_launch(void* const* d_in, const int* in_sizes, int n_in,
                              void* d_out, int out_size) {
    const float* cls = (const float*)d_in[0];   // [1, AN, NC]
    const float* reg = (const float*)d_in[1];   // [1, AN, 4]
    const float* anc = (const float*)d_in[2];   // [1, AN, 4]
    float* out = (float*)d_out;

    dim3 tg(AN / 64, (NC + 31) / 32);
    transpose_kernel<<<tg, 256>>>(cls);

    int selSmem = 16 * 1024 * 4 + CAP * 8;
    cudaFuncSetAttribute(select_kernel,
                         cudaFuncAttributeMaxDynamicSharedMemorySize, selSmem);
    select_kernel<<<NC, 1024, selSmem>>>(reg, anc);

    nms_mask_kernel<<<dim3(PARTS, NC), 128>>>();

    int redSmem = 32768 * 4;
    cudaFuncSetAttribute(nms_reduce_kernel,
                         cudaFuncAttributeMaxDynamicSharedMemorySize, redSmem);
    nms_reduce_kernel<<<NC, 1024, redSmem>>>(out);
}